// round 12
// baseline (speedup 1.0000x reference)
#include <cuda_runtime.h>
#include <cuda_bf16.h>
#include <math.h>
#include <stdint.h>

// Problem constants (fixed shapes)
#define TT   8192      // tokens = B*S = 4*2048
#define HH   2048      // hidden
#define II   1024      // intermediate
#define EE   16        // experts
#define KK   8         // top-k
#define RR   602       // lora rank

// ---------------- scratch (device globals; no allocation allowed) ----------
__device__ float d_base_g[TT * II];
__device__ float d_base_u[TT * II];
__device__ float d_gbuf  [TT * II];
__device__ float d_ubuf  [TT * II];
__device__ float d_hbuf  [TT * II];
__device__ float d_hacc  [TT * II];
__device__ float d_tg    [TT * RR];
__device__ float d_tu    [TT * RR];
__device__ float d_td    [TT * RR];
__device__ float d_logits[TT * EE];
__device__ float d_comb  [TT * EE];

// ---------------- helpers ---------------------------------------------------
// pack two floats to bf16x2: result.lo = bf16(lo_f), result.hi = bf16(hi_f)
__device__ __forceinline__ uint32_t cvt_bf16x2(float hi_f, float lo_f) {
    uint32_t r;
    asm("cvt.rn.bf16x2.f32 %0, %1, %2;" : "=r"(r) : "f"(hi_f), "f"(lo_f));
    return r;
}
__device__ __forceinline__ float bf16lo_to_f32(uint32_t p) {
    return __uint_as_float(p << 16);
}
__device__ __forceinline__ float bf16hi_to_f32(uint32_t p) {
    return __uint_as_float(p & 0xFFFF0000u);
}

#define MMA16816(c, a, b)                                                     \
    asm volatile(                                                             \
        "mma.sync.aligned.m16n8k16.row.col.f32.bf16.bf16.f32 "                \
        "{%0,%1,%2,%3}, {%4,%5,%6,%7}, {%8,%9}, {%0,%1,%2,%3};"               \
        : "+f"((c)[0]), "+f"((c)[1]), "+f"((c)[2]), "+f"((c)[3])              \
        : "r"((a)[0]), "r"((a)[1]), "r"((a)[2]), "r"((a)[3]),                 \
          "r"((b)[0]), "r"((b)[1]))

// ---------------- bf16-split tensor-core NT GEMM ---------------------------
// C[M,N] (+)= A[M,K] @ B[N,K]^T, fp32 in/out, bf16 hi/lo split (3 MMA passes)
// EPI: 0 -> C = acc ; 1 -> C += acc ; 2 -> C = acc + D
// Requires: K even, A/B/C/D 16B-aligned. Block tile 128x128x32, 256 threads.
template <int EPI>
__global__ __launch_bounds__(256, 1)
void hgemm_nt(const float* __restrict__ A,
              const float* __restrict__ B,
              float* __restrict__ C,
              const float* __restrict__ D,
              int M, int N, int K)
{
    // smem stores packed bf16x2 words: [row][kword], kword = k/2 (16 words = 32 k)
    // +2 words padding -> row stride 18 words (72B) to stagger banks
    __shared__ uint32_t Ah[128][18], Al[128][18], Bh[128][18], Bl[128][18];

    const int tid  = threadIdx.x;
    const int lane = tid & 31;
    const int warp = tid >> 5;
    const int g    = lane >> 2;     // 0..7
    const int tg   = lane & 3;      // 0..3
    const int wm   = (warp & 1) * 64;   // warp row base within block
    const int wn   = (warp >> 1) * 32;  // warp col base within block

    const int bm0 = blockIdx.y * 128;
    const int bn0 = blockIdx.x * 128;

    float acc[4][4][4];
#pragma unroll
    for (int a = 0; a < 4; a++)
#pragma unroll
        for (int b = 0; b < 4; b++)
#pragma unroll
            for (int c = 0; c < 4; c++) acc[a][b][c] = 0.f;

    for (int k0 = 0; k0 < K; k0 += 32) {
        // ---- load + convert + split: 128 rows x 16 kwords, 256 threads x 8 ----
#pragma unroll
        for (int j = 0; j < 8; j++) {
            int idx = tid + j * 256;        // 0..2047
            int r   = idx >> 4;             // 0..127
            int kw  = idx & 15;             // kword 0..15
            int k   = k0 + kw * 2;

            float2 av = make_float2(0.f, 0.f);
            if (bm0 + r < M && k < K)       // K even -> k<K implies k+1<K
                av = *reinterpret_cast<const float2*>(A + (size_t)(bm0 + r) * K + k);
            uint32_t ah = cvt_bf16x2(av.y, av.x);
            float arx = av.x - bf16lo_to_f32(ah);
            float ary = av.y - bf16hi_to_f32(ah);
            Ah[r][kw] = ah;
            Al[r][kw] = cvt_bf16x2(ary, arx);

            float2 bv = make_float2(0.f, 0.f);
            if (bn0 + r < N && k < K)
                bv = *reinterpret_cast<const float2*>(B + (size_t)(bn0 + r) * K + k);
            uint32_t bh = cvt_bf16x2(bv.y, bv.x);
            float brx = bv.x - bf16lo_to_f32(bh);
            float bry = bv.y - bf16hi_to_f32(bh);
            Bh[r][kw] = bh;
            Bl[r][kw] = cvt_bf16x2(bry, brx);
        }
        __syncthreads();

        // ---- compute: two k16 steps per chunk ----
#pragma unroll
        for (int ks = 0; ks < 2; ks++) {
            int w0 = ks * 8 + tg;           // kword for this thread's frag cols

            uint32_t aH[4][4], aL[4][4], bH[4][2], bL[4][2];
#pragma unroll
            for (int fm = 0; fm < 4; fm++) {
                int r = wm + fm * 16 + g;
                aH[fm][0] = Ah[r][w0];
                aH[fm][1] = Ah[r + 8][w0];
                aH[fm][2] = Ah[r][w0 + 4];
                aH[fm][3] = Ah[r + 8][w0 + 4];
                aL[fm][0] = Al[r][w0];
                aL[fm][1] = Al[r + 8][w0];
                aL[fm][2] = Al[r][w0 + 4];
                aL[fm][3] = Al[r + 8][w0 + 4];
            }
#pragma unroll
            for (int fn = 0; fn < 4; fn++) {
                int r = wn + fn * 8 + g;
                bH[fn][0] = Bh[r][w0];
                bH[fn][1] = Bh[r][w0 + 4];
                bL[fn][0] = Bl[r][w0];
                bL[fn][1] = Bl[r][w0 + 4];
            }
#pragma unroll
            for (int fm = 0; fm < 4; fm++)
#pragma unroll
                for (int fn = 0; fn < 4; fn++) {
                    MMA16816(acc[fm][fn], aH[fm], bH[fn]);   // hi*hi
                    MMA16816(acc[fm][fn], aL[fm], bH[fn]);   // lo*hi
                    MMA16816(acc[fm][fn], aH[fm], bL[fn]);   // hi*lo
                }
        }
        __syncthreads();
    }

    // ---- epilogue ----
#pragma unroll
    for (int fm = 0; fm < 4; fm++) {
        int r0 = bm0 + wm + fm * 16 + g;
#pragma unroll
        for (int fn = 0; fn < 4; fn++) {
            int c0 = bn0 + wn + fn * 8 + tg * 2;
            const float* a = acc[fm][fn];
#pragma unroll
            for (int half = 0; half < 2; half++) {
                int r = r0 + half * 8;
                if (r >= M) continue;
                float v0 = a[half * 2 + 0];
                float v1 = a[half * 2 + 1];
                size_t o0 = (size_t)r * N + c0;
                if (c0 < N) {
                    if (EPI == 0)      C[o0] = v0;
                    else if (EPI == 1) C[o0] += v0;
                    else               C[o0] = v0 + D[o0];
                }
                if (c0 + 1 < N) {
                    if (EPI == 0)      C[o0 + 1] = v1;
                    else if (EPI == 1) C[o0 + 1] += v1;
                    else               C[o0 + 1] = v1 + D[o0 + 1];
                }
            }
        }
    }
}

// ---------------- router logits: one block per token, 16 warps ------------
__global__ __launch_bounds__(512)
void router_logits_kernel(const float* __restrict__ x,
                          const float* __restrict__ w,
                          float* __restrict__ logits)
{
    int t    = blockIdx.x;
    int lane = threadIdx.x & 31;
    int e    = threadIdx.x >> 5;     // 0..15
    const float* xr = x + (size_t)t * HH;
    const float* wr = w + (size_t)e * HH;
    float s = 0.f;
    for (int i = lane; i < HH; i += 32) s = fmaf(xr[i], wr[i], s);
#pragma unroll
    for (int o = 16; o > 0; o >>= 1) s += __shfl_xor_sync(0xffffffffu, s, o);
    if (lane == 0) logits[(size_t)t * EE + e] = s;
}

// ---------------- softmax + top-8 + renorm -> dense combine [T,E] ---------
__global__ __launch_bounds__(256)
void combine_kernel(const float* __restrict__ logits, float* __restrict__ comb)
{
    int t = blockIdx.x * blockDim.x + threadIdx.x;
    if (t >= TT) return;
    float l[EE];
    float mx = -1e30f;
#pragma unroll
    for (int e = 0; e < EE; e++) { l[e] = logits[(size_t)t * EE + e]; mx = fmaxf(mx, l[e]); }
#pragma unroll
    for (int e = 0; e < EE; e++) l[e] = expf(l[e] - mx);
    bool sel[EE];
#pragma unroll
    for (int e = 0; e < EE; e++) sel[e] = false;
    float wsum = 0.f;
    for (int k = 0; k < KK; k++) {
        int   bi = -1;
        float bv = -1.f;
#pragma unroll
        for (int e = 0; e < EE; e++)
            if (!sel[e] && l[e] > bv) { bv = l[e]; bi = e; }
        sel[bi] = true;
        wsum += bv;
    }
    float inv = 1.f / wsum;
#pragma unroll
    for (int e = 0; e < EE; e++)
        comb[(size_t)t * EE + e] = sel[e] ? l[e] * inv : 0.f;
}

// ---------------- h = c * silu(g) * u ; hacc += h --------------------------
__global__ __launch_bounds__(256)
void h_kernel(const float* __restrict__ g, const float* __restrict__ u,
              const float* __restrict__ comb, int e,
              float* __restrict__ h, float* __restrict__ hacc)
{
    int idx = blockIdx.x * blockDim.x + threadIdx.x;
    if (idx >= TT * II) return;
    int t = idx >> 10;               // / II (1024)
    float c  = comb[(size_t)t * EE + e];
    float gv = g[idx];
    float sv = gv / (1.f + expf(-gv));
    float hv = c * sv * u[idx];
    h[idx]   = hv;
    hacc[idx] += hv;
}

__global__ __launch_bounds__(256)
void zero_kernel(float* __restrict__ p, int n)
{
    int i = blockIdx.x * blockDim.x + threadIdx.x;
    if (i < n) p[i] = 0.f;
}

__global__ __launch_bounds__(256)
void copy_kernel(const float* __restrict__ s, float* __restrict__ d, int n)
{
    int i = blockIdx.x * blockDim.x + threadIdx.x;
    if (i < n) d[i] = s[i];
}

// ---------------- launch ----------------------------------------------------
extern "C" void kernel_launch(void* const* d_in, const int* in_sizes, int n_in,
                              void* d_out, int out_size)
{
    const float* x   = (const float*)d_in[0];   // [T,H]
    const float* wr  = (const float*)d_in[1];   // [E,H]
    const float* Wg  = (const float*)d_in[2];   // [I,H]
    const float* Wu  = (const float*)d_in[3];   // [I,H]
    const float* Wd  = (const float*)d_in[4];   // [H,I]
    const float* Ag  = (const float*)d_in[5];   // [E,R,H]
    const float* Bg  = (const float*)d_in[6];   // [E,I,R]
    const float* Au  = (const float*)d_in[7];   // [E,R,H]
    const float* Bu  = (const float*)d_in[8];   // [E,I,R]
    const float* Ad  = (const float*)d_in[9];   // [E,R,I]
    const float* Bd  = (const float*)d_in[10];  // [E,H,R]
    float* out = (float*)d_out;

    float *base_g, *base_u, *gbuf, *ubuf, *hbuf, *hacc, *tg, *tu, *td, *logits, *comb;
    cudaGetSymbolAddress((void**)&base_g, d_base_g);
    cudaGetSymbolAddress((void**)&base_u, d_base_u);
    cudaGetSymbolAddress((void**)&gbuf,   d_gbuf);
    cudaGetSymbolAddress((void**)&ubuf,   d_ubuf);
    cudaGetSymbolAddress((void**)&hbuf,   d_hbuf);
    cudaGetSymbolAddress((void**)&hacc,   d_hacc);
    cudaGetSymbolAddress((void**)&tg,     d_tg);
    cudaGetSymbolAddress((void**)&tu,     d_tu);
    cudaGetSymbolAddress((void**)&td,     d_td);
    cudaGetSymbolAddress((void**)&logits, d_logits);
    cudaGetSymbolAddress((void**)&comb,   d_comb);

    const int TH = TT * HH;
    const int TI = TT * II;
    const int TE = TT * EE;

    // zero accumulators
    zero_kernel<<<(TH + 255) / 256, 256>>>(out, TH);
    zero_kernel<<<(TI + 255) / 256, 256>>>(hacc, TI);

    // router
    router_logits_kernel<<<TT, 512>>>(x, wr, logits);
    combine_kernel<<<(TT + 255) / 256, 256>>>(logits, comb);

    dim3 blk(256);
    auto grid = [](int M, int N) { return dim3((N + 127) / 128, (M + 127) / 128); };

    // shared base projections
    hgemm_nt<0><<<grid(TT, II), blk>>>(x, Wg, base_g, nullptr, TT, II, HH);
    hgemm_nt<0><<<grid(TT, II), blk>>>(x, Wu, base_u, nullptr, TT, II, HH);

    for (int e = 0; e < EE; e++) {
        const float* Ag_e = Ag + (size_t)e * RR * HH;
        const float* Bg_e = Bg + (size_t)e * II * RR;
        const float* Au_e = Au + (size_t)e * RR * HH;
        const float* Bu_e = Bu + (size_t)e * II * RR;
        const float* Ad_e = Ad + (size_t)e * RR * II;
        const float* Bd_e = Bd + (size_t)e * HH * RR;

        // g = base_g + (x @ Ag^T) @ Bg^T
        hgemm_nt<0><<<grid(TT, RR), blk>>>(x,  Ag_e, tg,   nullptr, TT, RR, HH);
        hgemm_nt<2><<<grid(TT, II), blk>>>(tg, Bg_e, gbuf, base_g,  TT, II, RR);
        // u = base_u + (x @ Au^T) @ Bu^T
        hgemm_nt<0><<<grid(TT, RR), blk>>>(x,  Au_e, tu,   nullptr, TT, RR, HH);
        hgemm_nt<2><<<grid(TT, II), blk>>>(tu, Bu_e, ubuf, base_u,  TT, II, RR);
        // h = c_e * silu(g) * u ; hacc += h   (fold combine weight into h)
        h_kernel<<<(TI + 255) / 256, 256>>>(gbuf, ubuf, comb, e, hbuf, hacc);
        // out += (h @ Ad^T) @ Bd^T
        hgemm_nt<0><<<grid(TT, RR), blk>>>(hbuf, Ad_e, td, nullptr, TT, RR, II);
        hgemm_nt<1><<<grid(TT, HH), blk>>>(td, Bd_e, out, nullptr, TT, HH, RR);
    }

    // shared down projection once: out += hacc @ Wd^T
    hgemm_nt<1><<<grid(TT, HH), blk>>>(hacc, Wd, out, nullptr, TT, HH, II);

    // router_logits is the second output, appended after out
    if (out_size >= TH + TE)
        copy_kernel<<<(TE + 255) / 256, 256>>>(logits, out + TH, TE);
}

// round 17
// speedup vs baseline: 1.0003x; 1.0003x over previous
#include <cuda_runtime.h>
#include <cuda_bf16.h>
#include <math.h>
#include <stdint.h>

// Problem constants (fixed shapes)
#define TT   8192      // tokens = B*S = 4*2048
#define HH   2048      // hidden
#define II   1024      // intermediate
#define EE   16        // experts
#define KK   8         // top-k
#define RR   602       // lora rank

// ---------------- scratch (device globals; no allocation allowed) ----------
__device__ float d_base_g[TT * II];
__device__ float d_base_u[TT * II];
__device__ float d_gbuf  [TT * II];
__device__ float d_ubuf  [TT * II];
__device__ float d_hbuf  [TT * II];
__device__ float d_hacc  [TT * II];
__device__ float d_tg    [TT * RR];
__device__ float d_tu    [TT * RR];
__device__ float d_td    [TT * RR];
__device__ float d_logits[TT * EE];
__device__ float d_comb  [TT * EE];

// ---------------- helpers ---------------------------------------------------
// pack two floats to bf16x2: result.lo = bf16(lo_f), result.hi = bf16(hi_f)
__device__ __forceinline__ uint32_t cvt_bf16x2(float hi_f, float lo_f) {
    uint32_t r;
    asm("cvt.rn.bf16x2.f32 %0, %1, %2;" : "=r"(r) : "f"(hi_f), "f"(lo_f));
    return r;
}
__device__ __forceinline__ float bf16lo_to_f32(uint32_t p) {
    return __uint_as_float(p << 16);
}
__device__ __forceinline__ float bf16hi_to_f32(uint32_t p) {
    return __uint_as_float(p & 0xFFFF0000u);
}

#define MMA16816(c, a, b)                                                     \
    asm volatile(                                                             \
        "mma.sync.aligned.m16n8k16.row.col.f32.bf16.bf16.f32 "                \
        "{%0,%1,%2,%3}, {%4,%5,%6,%7}, {%8,%9}, {%0,%1,%2,%3};"               \
        : "+f"((c)[0]), "+f"((c)[1]), "+f"((c)[2]), "+f"((c)[3])              \
        : "r"((a)[0]), "r"((a)[1]), "r"((a)[2]), "r"((a)[3]),                 \
          "r"((b)[0]), "r"((b)[1]))

// ---------------- bf16-split tensor-core NT GEMM ---------------------------
// C[M,N] (+)= A[M,K] @ B[N,K]^T, fp32 in/out, bf16 hi/lo split (3 MMA passes)
// EPI: 0 -> C = acc ; 1 -> C += acc ; 2 -> C = acc + D
// Requires: K even, A/B/C/D 16B-aligned. Block tile 128x128x32, 256 threads.
template <int EPI>
__global__ __launch_bounds__(256, 1)
void hgemm_nt(const float* __restrict__ A,
              const float* __restrict__ B,
              float* __restrict__ C,
              const float* __restrict__ D,
              int M, int N, int K)
{
    // smem stores packed bf16x2 words: [row][kword], kword = k/2 (16 words = 32 k)
    // +2 words padding -> row stride 18 words (72B) to stagger banks
    __shared__ uint32_t Ah[128][18], Al[128][18], Bh[128][18], Bl[128][18];

    const int tid  = threadIdx.x;
    const int lane = tid & 31;
    const int warp = tid >> 5;
    const int g    = lane >> 2;     // 0..7
    const int tg   = lane & 3;      // 0..3
    const int wm   = (warp & 1) * 64;   // warp row base within block
    const int wn   = (warp >> 1) * 32;  // warp col base within block

    const int bm0 = blockIdx.y * 128;
    const int bn0 = blockIdx.x * 128;

    float acc[4][4][4];
#pragma unroll
    for (int a = 0; a < 4; a++)
#pragma unroll
        for (int b = 0; b < 4; b++)
#pragma unroll
            for (int c = 0; c < 4; c++) acc[a][b][c] = 0.f;

    for (int k0 = 0; k0 < K; k0 += 32) {
        // ---- load + convert + split: 128 rows x 16 kwords, 256 threads x 8 ----
#pragma unroll
        for (int j = 0; j < 8; j++) {
            int idx = tid + j * 256;        // 0..2047
            int r   = idx >> 4;             // 0..127
            int kw  = idx & 15;             // kword 0..15
            int k   = k0 + kw * 2;

            float2 av = make_float2(0.f, 0.f);
            if (bm0 + r < M && k < K)       // K even -> k<K implies k+1<K
                av = *reinterpret_cast<const float2*>(A + (size_t)(bm0 + r) * K + k);
            uint32_t ah = cvt_bf16x2(av.y, av.x);
            float arx = av.x - bf16lo_to_f32(ah);
            float ary = av.y - bf16hi_to_f32(ah);
            Ah[r][kw] = ah;
            Al[r][kw] = cvt_bf16x2(ary, arx);

            float2 bv = make_float2(0.f, 0.f);
            if (bn0 + r < N && k < K)
                bv = *reinterpret_cast<const float2*>(B + (size_t)(bn0 + r) * K + k);
            uint32_t bh = cvt_bf16x2(bv.y, bv.x);
            float brx = bv.x - bf16lo_to_f32(bh);
            float bry = bv.y - bf16hi_to_f32(bh);
            Bh[r][kw] = bh;
            Bl[r][kw] = cvt_bf16x2(bry, brx);
        }
        __syncthreads();

        // ---- compute: two k16 steps per chunk ----
#pragma unroll
        for (int ks = 0; ks < 2; ks++) {
            int w0 = ks * 8 + tg;           // kword for this thread's frag cols

            uint32_t aH[4][4], aL[4][4], bH[4][2], bL[4][2];
#pragma unroll
            for (int fm = 0; fm < 4; fm++) {
                int r = wm + fm * 16 + g;
                aH[fm][0] = Ah[r][w0];
                aH[fm][1] = Ah[r + 8][w0];
                aH[fm][2] = Ah[r][w0 + 4];
                aH[fm][3] = Ah[r + 8][w0 + 4];
                aL[fm][0] = Al[r][w0];
                aL[fm][1] = Al[r + 8][w0];
                aL[fm][2] = Al[r][w0 + 4];
                aL[fm][3] = Al[r + 8][w0 + 4];
            }
#pragma unroll
            for (int fn = 0; fn < 4; fn++) {
                int r = wn + fn * 8 + g;
                bH[fn][0] = Bh[r][w0];
                bH[fn][1] = Bh[r][w0 + 4];
                bL[fn][0] = Bl[r][w0];
                bL[fn][1] = Bl[r][w0 + 4];
            }
#pragma unroll
            for (int fm = 0; fm < 4; fm++)
#pragma unroll
                for (int fn = 0; fn < 4; fn++) {
                    MMA16816(acc[fm][fn], aH[fm], bH[fn]);   // hi*hi
                    MMA16816(acc[fm][fn], aL[fm], bH[fn]);   // lo*hi
                    MMA16816(acc[fm][fn], aH[fm], bL[fn]);   // hi*lo
                }
        }
        __syncthreads();
    }

    // ---- epilogue ----
#pragma unroll
    for (int fm = 0; fm < 4; fm++) {
        int r0 = bm0 + wm + fm * 16 + g;
#pragma unroll
        for (int fn = 0; fn < 4; fn++) {
            int c0 = bn0 + wn + fn * 8 + tg * 2;
            const float* a = acc[fm][fn];
#pragma unroll
            for (int half = 0; half < 2; half++) {
                int r = r0 + half * 8;
                if (r >= M) continue;
                float v0 = a[half * 2 + 0];
                float v1 = a[half * 2 + 1];
                size_t o0 = (size_t)r * N + c0;
                if (c0 < N) {
                    if (EPI == 0)      C[o0] = v0;
                    else if (EPI == 1) C[o0] += v0;
                    else               C[o0] = v0 + D[o0];
                }
                if (c0 + 1 < N) {
                    if (EPI == 0)      C[o0 + 1] = v1;
                    else if (EPI == 1) C[o0 + 1] += v1;
                    else               C[o0 + 1] = v1 + D[o0 + 1];
                }
            }
        }
    }
}

// ---------------- router logits: one block per token, 16 warps ------------
__global__ __launch_bounds__(512)
void router_logits_kernel(const float* __restrict__ x,
                          const float* __restrict__ w,
                          float* __restrict__ logits)
{
    int t    = blockIdx.x;
    int lane = threadIdx.x & 31;
    int e    = threadIdx.x >> 5;     // 0..15
    const float* xr = x + (size_t)t * HH;
    const float* wr = w + (size_t)e * HH;
    float s = 0.f;
    for (int i = lane; i < HH; i += 32) s = fmaf(xr[i], wr[i], s);
#pragma unroll
    for (int o = 16; o > 0; o >>= 1) s += __shfl_xor_sync(0xffffffffu, s, o);
    if (lane == 0) logits[(size_t)t * EE + e] = s;
}

// ---------------- softmax + top-8 + renorm -> dense combine [T,E] ---------
__global__ __launch_bounds__(256)
void combine_kernel(const float* __restrict__ logits, float* __restrict__ comb)
{
    int t = blockIdx.x * blockDim.x + threadIdx.x;
    if (t >= TT) return;
    float l[EE];
    float mx = -1e30f;
#pragma unroll
    for (int e = 0; e < EE; e++) { l[e] = logits[(size_t)t * EE + e]; mx = fmaxf(mx, l[e]); }
#pragma unroll
    for (int e = 0; e < EE; e++) l[e] = expf(l[e] - mx);
    bool sel[EE];
#pragma unroll
    for (int e = 0; e < EE; e++) sel[e] = false;
    float wsum = 0.f;
    for (int k = 0; k < KK; k++) {
        int   bi = -1;
        float bv = -1.f;
#pragma unroll
        for (int e = 0; e < EE; e++)
            if (!sel[e] && l[e] > bv) { bv = l[e]; bi = e; }
        sel[bi] = true;
        wsum += bv;
    }
    float inv = 1.f / wsum;
#pragma unroll
    for (int e = 0; e < EE; e++)
        comb[(size_t)t * EE + e] = sel[e] ? l[e] * inv : 0.f;
}

// ---------------- h = c * silu(g) * u ; hacc += h --------------------------
__global__ __launch_bounds__(256)
void h_kernel(const float* __restrict__ g, const float* __restrict__ u,
              const float* __restrict__ comb, int e,
              float* __restrict__ h, float* __restrict__ hacc)
{
    int idx = blockIdx.x * blockDim.x + threadIdx.x;
    if (idx >= TT * II) return;
    int t = idx >> 10;               // / II (1024)
    float c  = comb[(size_t)t * EE + e];
    float gv = g[idx];
    float sv = gv / (1.f + expf(-gv));
    float hv = c * sv * u[idx];
    h[idx]   = hv;
    hacc[idx] += hv;
}

__global__ __launch_bounds__(256)
void zero_kernel(float* __restrict__ p, int n)
{
    int i = blockIdx.x * blockDim.x + threadIdx.x;
    if (i < n) p[i] = 0.f;
}

__global__ __launch_bounds__(256)
void copy_kernel(const float* __restrict__ s, float* __restrict__ d, int n)
{
    int i = blockIdx.x * blockDim.x + threadIdx.x;
    if (i < n) d[i] = s[i];
}

// ---------------- launch ----------------------------------------------------
extern "C" void kernel_launch(void* const* d_in, const int* in_sizes, int n_in,
                              void* d_out, int out_size)
{
    const float* x   = (const float*)d_in[0];   // [T,H]
    const float* wr  = (const float*)d_in[1];   // [E,H]
    const float* Wg  = (const float*)d_in[2];   // [I,H]
    const float* Wu  = (const float*)d_in[3];   // [I,H]
    const float* Wd  = (const float*)d_in[4];   // [H,I]
    const float* Ag  = (const float*)d_in[5];   // [E,R,H]
    const float* Bg  = (const float*)d_in[6];   // [E,I,R]
    const float* Au  = (const float*)d_in[7];   // [E,R,H]
    const float* Bu  = (const float*)d_in[8];   // [E,I,R]
    const float* Ad  = (const float*)d_in[9];   // [E,R,I]
    const float* Bd  = (const float*)d_in[10];  // [E,H,R]
    float* out = (float*)d_out;

    float *base_g, *base_u, *gbuf, *ubuf, *hbuf, *hacc, *tg, *tu, *td, *logits, *comb;
    cudaGetSymbolAddress((void**)&base_g, d_base_g);
    cudaGetSymbolAddress((void**)&base_u, d_base_u);
    cudaGetSymbolAddress((void**)&gbuf,   d_gbuf);
    cudaGetSymbolAddress((void**)&ubuf,   d_ubuf);
    cudaGetSymbolAddress((void**)&hbuf,   d_hbuf);
    cudaGetSymbolAddress((void**)&hacc,   d_hacc);
    cudaGetSymbolAddress((void**)&tg,     d_tg);
    cudaGetSymbolAddress((void**)&tu,     d_tu);
    cudaGetSymbolAddress((void**)&td,     d_td);
    cudaGetSymbolAddress((void**)&logits, d_logits);
    cudaGetSymbolAddress((void**)&comb,   d_comb);

    const int TH = TT * HH;
    const int TI = TT * II;
    const int TE = TT * EE;

    // zero accumulators
    zero_kernel<<<(TH + 255) / 256, 256>>>(out, TH);
    zero_kernel<<<(TI + 255) / 256, 256>>>(hacc, TI);

    // router
    router_logits_kernel<<<TT, 512>>>(x, wr, logits);
    combine_kernel<<<(TT + 255) / 256, 256>>>(logits, comb);

    dim3 blk(256);
    auto grid = [](int M, int N) { return dim3((N + 127) / 128, (M + 127) / 128); };

    // shared base projections
    hgemm_nt<0><<<grid(TT, II), blk>>>(x, Wg, base_g, nullptr, TT, II, HH);
    hgemm_nt<0><<<grid(TT, II), blk>>>(x, Wu, base_u, nullptr, TT, II, HH);

    for (int e = 0; e < EE; e++) {
        const float* Ag_e = Ag + (size_t)e * RR * HH;
        const float* Bg_e = Bg + (size_t)e * II * RR;
        const float* Au_e = Au + (size_t)e * RR * HH;
        const float* Bu_e = Bu + (size_t)e * II * RR;
        const float* Ad_e = Ad + (size_t)e * RR * II;
        const float* Bd_e = Bd + (size_t)e * HH * RR;

        // g = base_g + (x @ Ag^T) @ Bg^T
        hgemm_nt<0><<<grid(TT, RR), blk>>>(x,  Ag_e, tg,   nullptr, TT, RR, HH);
        hgemm_nt<2><<<grid(TT, II), blk>>>(tg, Bg_e, gbuf, base_g,  TT, II, RR);
        // u = base_u + (x @ Au^T) @ Bu^T
        hgemm_nt<0><<<grid(TT, RR), blk>>>(x,  Au_e, tu,   nullptr, TT, RR, HH);
        hgemm_nt<2><<<grid(TT, II), blk>>>(tu, Bu_e, ubuf, base_u,  TT, II, RR);
        // h = c_e * silu(g) * u ; hacc += h   (fold combine weight into h)
        h_kernel<<<(TI + 255) / 256, 256>>>(gbuf, ubuf, comb, e, hbuf, hacc);
        // out += (h @ Ad^T) @ Bd^T
        hgemm_nt<0><<<grid(TT, RR), blk>>>(hbuf, Ad_e, td, nullptr, TT, RR, II);
        hgemm_nt<1><<<grid(TT, HH), blk>>>(td, Bd_e, out, nullptr, TT, HH, RR);
    }

    // shared down projection once: out += hacc @ Wd^T
    hgemm_nt<1><<<grid(TT, HH), blk>>>(hacc, Wd, out, nullptr, TT, HH, II);

    // router_logits is the second output, appended after out
    if (out_size >= TH + TE)
        copy_kernel<<<(TE + 255) / 256, 256>>>(logits, out + TH, TE);
}